// round 1
// baseline (speedup 1.0000x reference)
#include <cuda_runtime.h>
#include <cuda_bf16.h>
#include <math.h>
#include <stdint.h>

// Problem constants (fixed by the dataset)
#define TT 5
#define FIN 10
#define HID 16
#define CC 2
#define MAXN 100000
#define MAXE 3200000
#define W1COLS (TT*FIN)   // 50
#define W2COLS (TT*HID)   // 80

// ---------------- device scratch (static: no allocation allowed) ----------------
__device__ int   g_cnt[MAXN];
__device__ int   g_rowptr[MAXN + 1];
__device__ int   g_cursor[MAXN];
__device__ int   g_bsum[256];
__device__ float g_dis[MAXN];
__device__ float g_dinv[MAXN];
__device__ int   g_csrc[MAXE];
__device__ float g_cw[MAXE];
__device__ float g_xT[(size_t)MAXN * W1COLS];
__device__ float g_agg[(size_t)MAXN * W2COLS];
__device__ float g_h1[(size_t)MAXN * W2COLS];
__device__ float g_feats[(size_t)MAXN * W2COLS];
__device__ float g_Mz[256], g_Mr[256], g_Mh[256];
__device__ float g_Bz[16],  g_Br[16],  g_Bh[16];

// ---------------- CSR build ----------------
__global__ void kzero(int* cnt, int n) {
    int i = blockIdx.x * blockDim.x + threadIdx.x;
    if (i < n) cnt[i] = 0;
}

__global__ void kcount(const int* __restrict__ dst, int* cnt, int e) {
    int i = blockIdx.x * blockDim.x + threadIdx.x;
    if (i < e) atomicAdd(&cnt[dst[i]], 1);
}

__global__ void knorm(const int* __restrict__ cnt, float* dis, float* dinv, int n) {
    int i = blockIdx.x * blockDim.x + threadIdx.x;
    if (i < n) {
        float deg = (float)cnt[i] + 1.0f;
        dis[i]  = rsqrtf(deg);
        dinv[i] = 1.0f / deg;
    }
}

// block-level inclusive scan of cnt into rowptr[1..], chunk = 512
__global__ void kscan_block(const int* __restrict__ cnt, int* rowptr, int* bsum, int n) {
    __shared__ int sh[512];
    int base = blockIdx.x * 512;
    int i = base + threadIdx.x;
    int v = (i < n) ? cnt[i] : 0;
    sh[threadIdx.x] = v;
    __syncthreads();
    for (int off = 1; off < 512; off <<= 1) {
        int t = (threadIdx.x >= off) ? sh[threadIdx.x - off] : 0;
        __syncthreads();
        sh[threadIdx.x] += t;
        __syncthreads();
    }
    if (i < n) rowptr[i + 1] = sh[threadIdx.x];
    if (threadIdx.x == 511) bsum[blockIdx.x] = sh[511];
}

// single-block exclusive scan of block sums (nb <= 256)
__global__ void kscan_bsum(int* bsum, int nb) {
    __shared__ int sh[256];
    int tid = threadIdx.x;
    int v = (tid < nb) ? bsum[tid] : 0;
    sh[tid] = v;
    __syncthreads();
    for (int off = 1; off < 256; off <<= 1) {
        int t = (tid >= off) ? sh[tid - off] : 0;
        __syncthreads();
        sh[tid] += t;
        __syncthreads();
    }
    if (tid < nb) bsum[tid] = sh[tid] - v;  // exclusive
}

__global__ void kscan_add(int* rowptr, const int* __restrict__ bsum, int n) {
    int i = blockIdx.x * blockDim.x + threadIdx.x;
    if (i < n) rowptr[i + 1] += bsum[i >> 9];
    if (i == 0) rowptr[0] = 0;
}

__global__ void kcursor(const int* __restrict__ rowptr, int* cursor, int n) {
    int i = blockIdx.x * blockDim.x + threadIdx.x;
    if (i < n) cursor[i] = rowptr[i];
}

__global__ void kfill(const int* __restrict__ src, const int* __restrict__ dst,
                      const float* __restrict__ dis, int* cursor,
                      int* csrc, float* cw, int e) {
    int i = blockIdx.x * blockDim.x + threadIdx.x;
    if (i < e) {
        int s = src[i], d = dst[i];
        int pos = atomicAdd(&cursor[d], 1);
        csrc[pos] = s;
        cw[pos]   = dis[s] * dis[d];
    }
}

// ---------------- transpose x [T,N,F] -> xT [N, T*F] ----------------
__global__ void kxt(const float* __restrict__ x, float* __restrict__ xT, int n) {
    int i = blockIdx.x * blockDim.x + threadIdx.x;
    if (i >= n * W1COLS) return;
    int node = i / W1COLS;
    int c = i - node * W1COLS;
    int t = c / FIN;
    int f = c - t * FIN;
    xT[i] = x[((size_t)t * n + node) * FIN + f];
}

// ---------------- propagation: out[d] = sum_in enorm * in[src] + dinv[d]*in[d] ----
// warp per destination node, W columns spread across lanes
template <int W>
__global__ __launch_bounds__(256) void kprop(const float* __restrict__ in,
                                             float* __restrict__ out,
                                             const int* __restrict__ rowptr,
                                             const int* __restrict__ csrc,
                                             const float* __restrict__ cw,
                                             const float* __restrict__ dinv, int n) {
    int warp = (blockIdx.x * blockDim.x + threadIdx.x) >> 5;
    if (warp >= n) return;
    int lane = threadIdx.x & 31;
    constexpr int NV = (W + 31) / 32;
    float acc[NV];
#pragma unroll
    for (int v = 0; v < NV; v++) acc[v] = 0.f;

    int r0 = rowptr[warp], r1 = rowptr[warp + 1];
    int deg = r1 - r0;
    int full = deg & ~31;

    for (int base = r0; base < r0 + full; base += 32) {
        int s   = csrc[base + lane];
        float w = cw[base + lane];
#pragma unroll 4
        for (int k = 0; k < 32; k++) {
            int   ss = __shfl_sync(0xffffffffu, s, k);
            float ww = __shfl_sync(0xffffffffu, w, k);
            const float* row = in + (size_t)ss * W;
#pragma unroll
            for (int v = 0; v < NV; v++) {
                int c = v * 32 + lane;
                float xv = (c < W) ? __ldg(row + c) : 0.f;
                acc[v] = fmaf(ww, xv, acc[v]);
            }
        }
    }
    int rem = deg - full;
    if (rem) {
        int base = r0 + full;
        int s = 0; float w = 0.f;
        if (lane < rem) { s = csrc[base + lane]; w = cw[base + lane]; }
        for (int k = 0; k < rem; k++) {
            int   ss = __shfl_sync(0xffffffffu, s, k);
            float ww = __shfl_sync(0xffffffffu, w, k);
            const float* row = in + (size_t)ss * W;
#pragma unroll
            for (int v = 0; v < NV; v++) {
                int c = v * 32 + lane;
                float xv = (c < W) ? __ldg(row + c) : 0.f;
                acc[v] = fmaf(ww, xv, acc[v]);
            }
        }
    }
    // self-loop term + write
    float di = dinv[warp];
    const float* srow = in + (size_t)warp * W;
    float* orow = out + (size_t)warp * W;
#pragma unroll
    for (int v = 0; v < NV; v++) {
        int c = v * 32 + lane;
        if (c < W) orow[c] = acc[v] + di * __ldg(srow + c);
    }
}

// ---------------- per-(node,t,h) dense transform: relu(agg @ W + b) --------------
template <int IN, int SIN>
__global__ __launch_bounds__(256) void ktrans(const float* __restrict__ agg,
                                              const float* __restrict__ W,
                                              const float* __restrict__ b,
                                              float* __restrict__ out, int n) {
    __shared__ float sW[IN * 16];
    __shared__ float sb[16];
    for (int i = threadIdx.x; i < IN * 16; i += blockDim.x) sW[i] = W[i];
    if (threadIdx.x < 16) sb[threadIdx.x] = b[threadIdx.x];
    __syncthreads();
    int idx = blockIdx.x * blockDim.x + threadIdx.x;
    if (idx >= n * TT * 16) return;
    int h = idx & 15;
    int nt = idx >> 4;
    int t = nt % TT;
    int node = nt / TT;
    const float* a = agg + (size_t)node * SIN + t * IN;
    float acc = sb[h];
#pragma unroll
    for (int k = 0; k < IN; k++) acc = fmaf(__ldg(a + k), sW[k * 16 + h], acc);
    out[(size_t)node * W2COLS + t * 16 + h] = fmaxf(acc, 0.f);
}

// ---------------- fold gate matmuls: M* = W* @ L*[0:16], B* = b*@L*[0:16] + l* ----
__global__ void kprep(const float* Wz, const float* bz, const float* Wr, const float* br,
                      const float* Wh, const float* bh,
                      const float* Lz, const float* lz, const float* Lr, const float* lr,
                      const float* Lh, const float* lh) {
    int tid = threadIdx.x;  // 256
    int k = tid >> 4, h = tid & 15;
    float mz = 0.f, mr = 0.f, mh = 0.f;
#pragma unroll
    for (int j = 0; j < 16; j++) {
        mz += Wz[k * 16 + j] * Lz[j * 16 + h];
        mr += Wr[k * 16 + j] * Lr[j * 16 + h];
        mh += Wh[k * 16 + j] * Lh[j * 16 + h];
    }
    g_Mz[tid] = mz; g_Mr[tid] = mr; g_Mh[tid] = mh;
    if (tid < 16) {
        float az = lz[tid], ar = lr[tid], ah = lh[tid];
#pragma unroll
        for (int j = 0; j < 16; j++) {
            az += bz[j] * Lz[j * 16 + tid];
            ar += br[j] * Lr[j * 16 + tid];
            ah += bh[j] * Lh[j * 16 + tid];
        }
        g_Bz[tid] = az; g_Br[tid] = ar; g_Bh[tid] = ah;
    }
}

// ---------------- GRU + attention pooling + FC + log_softmax ---------------------
#define GRU_NPB 96
__global__ __launch_bounds__(GRU_NPB) void kgru(const float* __restrict__ P,
                                                const float* __restrict__ Lz,
                                                const float* __restrict__ Lr,
                                                const float* __restrict__ Lh,
                                                const float* __restrict__ att,
                                                const float* __restrict__ fcW,
                                                const float* __restrict__ fcb,
                                                float* __restrict__ out, int n) {
    __shared__ float sP[GRU_NPB * 81];
    __shared__ float sMz[256], sMr[256], sMh[256];
    __shared__ float sLz[256], sLr[256], sLh[256];
    __shared__ float sBz[16], sBr[16], sBh[16];
    __shared__ float sfcW[32], sfcb[2], sprob[TT];

    int tid = threadIdx.x;
    for (int i = tid; i < 256; i += GRU_NPB) {
        sMz[i] = g_Mz[i]; sMr[i] = g_Mr[i]; sMh[i] = g_Mh[i];
        sLz[i] = Lz[256 + i]; sLr[i] = Lr[256 + i]; sLh[i] = Lh[256 + i];
    }
    if (tid < 16) { sBz[tid] = g_Bz[tid]; sBr[tid] = g_Br[tid]; sBh[tid] = g_Bh[tid]; }
    if (tid < 32) sfcW[tid] = fcW[tid];
    if (tid < 2)  sfcb[tid] = fcb[tid];
    if (tid == 0) {
        float m = att[0];
        for (int t = 1; t < TT; t++) m = fmaxf(m, att[t]);
        float ex[TT]; float s = 0.f;
        for (int t = 0; t < TT; t++) { ex[t] = expf(att[t] - m); s += ex[t]; }
        for (int t = 0; t < TT; t++) sprob[t] = ex[t] / s;
    }
    int base = blockIdx.x * GRU_NPB;
    for (int i = tid; i < GRU_NPB * W2COLS; i += GRU_NPB) {
        int nd = i / W2COLS, c = i - nd * W2COLS;
        int g = base + nd;
        sP[nd * 81 + c] = (g < n) ? P[(size_t)g * W2COLS + c] : 0.f;
    }
    __syncthreads();

    int node = base + tid;
    if (node >= n) return;
    const float* myP = &sP[tid * 81];

    float H[16], Hacc[16];
#pragma unroll
    for (int h = 0; h < 16; h++) { H[h] = 0.f; Hacc[h] = 0.f; }

#pragma unroll 1
    for (int t = 0; t < TT; t++) {
        float p[16];
#pragma unroll
        for (int k = 0; k < 16; k++) p[k] = myP[t * 16 + k];

        float a[16];
        // Z gate: a = p@Mz + H@Lz2 + Bz
#pragma unroll
        for (int h = 0; h < 16; h++) a[h] = sBz[h];
#pragma unroll
        for (int k = 0; k < 16; k++) {
            float pk = p[k], hk = H[k];
#pragma unroll
            for (int h = 0; h < 16; h++)
                a[h] += pk * sMz[k * 16 + h] + hk * sLz[k * 16 + h];
        }
        float Zg[16];
#pragma unroll
        for (int h = 0; h < 16; h++) Zg[h] = 1.f / (1.f + expf(-a[h]));

        // R gate
#pragma unroll
        for (int h = 0; h < 16; h++) a[h] = sBr[h];
#pragma unroll
        for (int k = 0; k < 16; k++) {
            float pk = p[k], hk = H[k];
#pragma unroll
            for (int h = 0; h < 16; h++)
                a[h] += pk * sMr[k * 16 + h] + hk * sLr[k * 16 + h];
        }
        float Rg[16];
#pragma unroll
        for (int h = 0; h < 16; h++) Rg[h] = 1.f / (1.f + expf(-a[h]));

        // candidate: a = p@Mh + (H*Rg)@Lh2 + Bh
#pragma unroll
        for (int h = 0; h < 16; h++) a[h] = sBh[h];
#pragma unroll
        for (int k = 0; k < 16; k++) {
            float pk = p[k], hr = H[k] * Rg[k];
#pragma unroll
            for (int h = 0; h < 16; h++)
                a[h] += pk * sMh[k * 16 + h] + hr * sLh[k * 16 + h];
        }
#pragma unroll
        for (int h = 0; h < 16; h++) {
            float ht = tanhf(a[h]);
            H[h] = Zg[h] * H[h] + (1.f - Zg[h]) * ht;
            Hacc[h] = fmaf(sprob[t], H[h], Hacc[h]);
        }
    }

    float l0 = sfcb[0], l1 = sfcb[1];
#pragma unroll
    for (int h = 0; h < 16; h++) {
        l0 = fmaf(Hacc[h], sfcW[h * 2 + 0], l0);
        l1 = fmaf(Hacc[h], sfcW[h * 2 + 1], l1);
    }
    float m = fmaxf(l0, l1);
    float lse = m + logf(expf(l0 - m) + expf(l1 - m));
    out[(size_t)node * 2 + 0] = l0 - lse;
    out[(size_t)node * 2 + 1] = l1 - lse;
}

// ---------------- launch ----------------
extern "C" void kernel_launch(void* const* d_in, const int* in_sizes, int n_in,
                              void* d_out, int out_size) {
    const float* x   = (const float*)d_in[0];
    const int*   src = (const int*)d_in[1];
    const int*   dst = (const int*)d_in[2];
    const float* W1  = (const float*)d_in[3];
    const float* b1  = (const float*)d_in[4];
    const float* W2  = (const float*)d_in[5];
    const float* b2  = (const float*)d_in[6];
    const float* Wz  = (const float*)d_in[7];
    const float* bz  = (const float*)d_in[8];
    const float* Wr  = (const float*)d_in[9];
    const float* br  = (const float*)d_in[10];
    const float* Wh  = (const float*)d_in[11];
    const float* bh  = (const float*)d_in[12];
    const float* Lz  = (const float*)d_in[13];
    const float* lz  = (const float*)d_in[14];
    const float* Lr  = (const float*)d_in[15];
    const float* lr  = (const float*)d_in[16];
    const float* Lh  = (const float*)d_in[17];
    const float* lh  = (const float*)d_in[18];
    const float* att = (const float*)d_in[19];
    const float* fcW = (const float*)d_in[20];
    const float* fcb = (const float*)d_in[21];

    int n = in_sizes[0] / (TT * FIN);
    int e = in_sizes[1];

    void* p;
    cudaGetSymbolAddress(&p, g_cnt);     int*   cnt    = (int*)p;
    cudaGetSymbolAddress(&p, g_rowptr);  int*   rowptr = (int*)p;
    cudaGetSymbolAddress(&p, g_cursor);  int*   cursor = (int*)p;
    cudaGetSymbolAddress(&p, g_bsum);    int*   bsum   = (int*)p;
    cudaGetSymbolAddress(&p, g_dis);     float* dis    = (float*)p;
    cudaGetSymbolAddress(&p, g_dinv);    float* dinv   = (float*)p;
    cudaGetSymbolAddress(&p, g_csrc);    int*   csrc   = (int*)p;
    cudaGetSymbolAddress(&p, g_cw);      float* cw     = (float*)p;
    cudaGetSymbolAddress(&p, g_xT);      float* xT     = (float*)p;
    cudaGetSymbolAddress(&p, g_agg);     float* agg    = (float*)p;
    cudaGetSymbolAddress(&p, g_h1);      float* h1     = (float*)p;
    cudaGetSymbolAddress(&p, g_feats);   float* feats  = (float*)p;

    int nb256_n = (n + 255) / 256;
    int nb256_e = (e + 255) / 256;
    int nblk    = (n + 511) / 512;

    // CSR build
    kzero<<<nb256_n, 256>>>(cnt, n);
    kcount<<<nb256_e, 256>>>(dst, cnt, e);
    knorm<<<nb256_n, 256>>>(cnt, dis, dinv, n);
    kscan_block<<<nblk, 512>>>(cnt, rowptr, bsum, n);
    kscan_bsum<<<1, 256>>>(bsum, nblk);
    kscan_add<<<nb256_n, 256>>>(rowptr, bsum, n);
    kcursor<<<nb256_n, 256>>>(rowptr, cursor, n);
    kfill<<<nb256_e, 256>>>(src, dst, dis, cursor, csrc, cw, e);

    // stage 0: transpose x
    kxt<<<(n * W1COLS + 255) / 256, 256>>>(x, xT, n);

    int prop_blocks = (n * 32 + 255) / 256;
    int tr_blocks   = (n * TT * 16 + 255) / 256;

    // stage 1: h1 = relu((S x) @ W1 + b1)
    kprop<W1COLS><<<prop_blocks, 256>>>(xT, agg, rowptr, csrc, cw, dinv, n);
    ktrans<FIN, W1COLS><<<tr_blocks, 256>>>(agg, W1, b1, h1, n);

    // stage 2: feats = relu((S h1) @ W2 + b2)
    kprop<W2COLS><<<prop_blocks, 256>>>(h1, agg, rowptr, csrc, cw, dinv, n);
    ktrans<HID, W2COLS><<<tr_blocks, 256>>>(agg, W2, b2, feats, n);

    // stage 3: P = S feats (shared by all three GRU gates)
    kprop<W2COLS><<<prop_blocks, 256>>>(feats, agg, rowptr, csrc, cw, dinv, n);

    // GRU + attention + FC + log_softmax
    kprep<<<1, 256>>>(Wz, bz, Wr, br, Wh, bh, Lz, lz, Lr, lr, Lh, lh);
    kgru<<<(n + GRU_NPB - 1) / GRU_NPB, GRU_NPB>>>(agg, Lz, Lr, Lh, att, fcW, fcb,
                                                   (float*)d_out, n);
}